// round 1
// baseline (speedup 1.0000x reference)
#include <cuda_runtime.h>
#include <math.h>

// Problem constants
#define HH 768
#define WW 768
#define NIMG 32
#define HWLL (768LL * 768LL)

// Tiling: block (32,8) threads, each thread produces 8 rows -> tile 32x64
#define BX 32
#define BYT 8
#define RPT 8
#define TILE_W BX
#define TILE_H (BYT * RPT)
#define SW (TILE_W + 4)   // 36
#define SH (TILE_H + 4)   // 68

#define MIN_WEIGHT 0.1f
#define INV_LOG2 1.4426950408889634f

__device__ double g_sums[NIMG];

__global__ void k_zero_sums() {
    if (threadIdx.x < NIMG) g_sums[threadIdx.x] = 0.0;
}

__global__ __launch_bounds__(BX * BYT) void k_pass1(
    const float* __restrict__ yd,
    const float* __restrict__ ygt,
    float* __restrict__ out)
{
    __shared__ float sp[SH][SW];      // sigmoid(p) tile with halo=2, OOB=0
    __shared__ float wsum[BYT];

    const int img  = blockIdx.z;
    const int col0 = blockIdx.x * TILE_W;
    const int row0 = blockIdx.y * TILE_H;
    const float* yimg = yd + (long long)img * HWLL;
    const float* gimg = ygt + (long long)img * HWLL;
    float* oimg = out + (long long)img * HWLL;

    const int tid = threadIdx.y * BX + threadIdx.x;

    // ---- cooperative fill of p = sigmoid(y) tile (halo 2, OOB -> 0) ----
    #pragma unroll
    for (int t = tid; t < SH * SW; t += BX * BYT) {
        int li = t / SW, lj = t % SW;
        int gi = row0 + li - 2, gj = col0 + lj - 2;
        float v = 0.0f;
        if ((unsigned)gi < (unsigned)HH && (unsigned)gj < (unsigned)WW) {
            float yv = __ldg(&yimg[gi * WW + gj]);
            v = 1.0f / (1.0f + __expf(-yv));
        }
        sp[li][lj] = v;
    }
    __syncthreads();

    const int j   = threadIdx.x;        // local output column
    const int gj  = col0 + j;           // global column
    const int li0 = threadIdx.y * RPT;  // first local output row (tile coords)

    // per-column valid-count factor (analytic, replaces per-neighbor checks)
    const int cntx = min(gj, 2) + min(WW - 1 - gj, 2) + 1;

    float hs[5], hq[5], pc[5];          // rolling rows: sum, sum-of-squares, center p
    float lsum = 0.0f;

    #pragma unroll
    for (int k = 0; k < RPT + 4; ++k) {
        const int r = li0 + k;          // smem row
        float a0 = sp[r][j + 0];
        float a1 = sp[r][j + 1];
        float a2 = sp[r][j + 2];
        float a3 = sp[r][j + 3];
        float a4 = sp[r][j + 4];
        hs[k % 5] = a0 + a1 + a2 + a3 + a4;
        hq[k % 5] = a0 * a0 + a1 * a1 + a2 * a2 + a3 * a3 + a4 * a4;
        pc[k % 5] = a2;

        if (k >= 4) {
            const int li = li0 + k - 4;     // local output row
            const int gi = row0 + li;       // global row
            const float S  = hs[0] + hs[1] + hs[2] + hs[3] + hs[4];
            const float Q  = hq[0] + hq[1] + hq[2] + hq[3] + hq[4];
            const float p0 = pc[(k - 2) % 5];

            const int cnty = min(gi, 2) + min(HH - 1 - gi, 2) + 1;
            const float fnv = (float)(cntx * cnty);   // window cells incl. center
            // acc = sum over valid neighbors (p0 - pn)^2 = nv*p0^2 - 2*p0*S + Q
            const float acc  = fmaf(fmaf(fnv, p0, -2.0f * S), p0, Q);
            const float cons = 1.0f - acc / (fnv - 1.0f);

            // entropy = 1 + (p0*y - softplus(y)) / ln2
            const float y   = __ldg(&yimg[gi * WW + gj]);   // L1 hit (just loaded by block)
            const float spv = fmaxf(y, 0.0f) + log1pf(__expf(-fabsf(y)));
            const float ent = 1.0f + (p0 * y - spv) * INV_LOG2;

            float w = cons * ent;
            w = fmaxf(w, __ldg(&gimg[gi * WW + gj]));
            w = fmaf(1.0f - MIN_WEIGHT, w, MIN_WEIGHT);

            oimg[gi * WW + gj] = w;
            lsum += w;
        }
    }

    // ---- block reduction of lsum, one double atomic per block ----
    #pragma unroll
    for (int o = 16; o; o >>= 1) lsum += __shfl_down_sync(0xffffffffu, lsum, o);
    if ((tid & 31) == 0) wsum[tid >> 5] = lsum;
    __syncthreads();
    if (tid < BYT) {
        float v = wsum[tid];
        #pragma unroll
        for (int o = BYT / 2; o; o >>= 1) v += __shfl_down_sync(0xffu, v, o);
        if (tid == 0) atomicAdd(&g_sums[img], (double)v);
    }
}

// in-place per-image normalization: out *= HW / sum[img]
__global__ __launch_bounds__(256) void k_pass2(float* __restrict__ out) {
    const int img = blockIdx.y;
    const float scale = (float)((double)HWLL / g_sums[img]);
    float4* p = reinterpret_cast<float4*>(out + (long long)img * HWLL);
    const int idx = blockIdx.x * blockDim.x + threadIdx.x;
    float4 v = p[idx];
    v.x *= scale; v.y *= scale; v.z *= scale; v.w *= scale;
    p[idx] = v;
}

extern "C" void kernel_launch(void* const* d_in, const int* in_sizes, int n_in,
                              void* d_out, int out_size) {
    const float* yd  = (const float*)d_in[0];
    const float* ygt = (const float*)d_in[1];
    float* out = (float*)d_out;

    k_zero_sums<<<1, 32>>>();

    dim3 b1(BX, BYT);
    dim3 g1(WW / TILE_W, HH / TILE_H, NIMG);   // (24, 12, 32)
    k_pass1<<<g1, b1>>>(yd, ygt, out);

    dim3 g2((int)(HWLL / 4 / 256), NIMG);      // (576, 32)
    k_pass2<<<g2, 256>>>(out);
}

// round 2
// speedup vs baseline: 1.1449x; 1.1449x over previous
#include <cuda_runtime.h>
#include <math.h>

// Problem constants
#define HH 768
#define WW 768
#define NIMG 32
#define HWI (768 * 768)
#define HWLL (768LL * 768LL)

// Tile: 128 cols x 64 rows per block; block (32,8); thread = 4 cols x 8 rows
#define TW 128
#define TH 64
#define SW2 136          // TW + 8 (4-col halo both sides, float4 aligned)
#define SH2 68           // TH + 4
#define BLOCKS_X (WW / TW)   // 6
#define BLOCKS_Y (HH / TH)   // 12
#define BPI (BLOCKS_X * BLOCKS_Y)  // 72 blocks per image

#define MIN_WEIGHT 0.1f
#define INV_LOG2 1.4426950408889634f

__device__ float g_part[NIMG * BPI];   // every slot written each run -> no init needed

__device__ __forceinline__ float sigm(float x) {
    return __fdividef(1.0f, 1.0f + __expf(-x));
}

__global__ __launch_bounds__(256) void k_pass1(
    const float* __restrict__ yd,
    const float* __restrict__ ygt,
    float* __restrict__ out)
{
    __shared__ float sp[SH2][SW2];
    __shared__ float wsum[8];

    const int img  = blockIdx.z;
    const int col0 = blockIdx.x * TW;
    const int row0 = blockIdx.y * TH;
    const float* __restrict__ yimg = yd  + (long long)img * HWLL;
    const float* __restrict__ gimg = ygt + (long long)img * HWLL;
    float* __restrict__ oimg = out + (long long)img * HWLL;

    const int tid = threadIdx.y * 32 + threadIdx.x;

    // ---- fill p = sigmoid(y) tile (halo: 2 rows, 4 cols; OOB -> 0) ----
    // 68 rows x 34 float4 = 2312 vector elements; halo float4s are fully
    // in-bounds or fully out-of-bounds (col0 is 128-aligned).
    for (int t = tid; t < SH2 * 34; t += 256) {
        const int li = t / 34;
        const int v  = t - li * 34;
        const int gi = row0 + li - 2;
        const int gj = col0 + v * 4 - 4;
        float4 r = make_float4(0.f, 0.f, 0.f, 0.f);
        if ((unsigned)gi < (unsigned)HH && (unsigned)gj <= (unsigned)(WW - 4)) {
            float4 yv = *reinterpret_cast<const float4*>(yimg + gi * WW + gj);
            r.x = sigm(yv.x); r.y = sigm(yv.y); r.z = sigm(yv.z); r.w = sigm(yv.w);
        }
        *reinterpret_cast<float4*>(&sp[li][v * 4]) = r;
    }
    __syncthreads();

    const int j    = threadIdx.x;
    const int gj0  = col0 + j * 4;           // first global output column
    const int r0   = threadIdx.y * 8;        // first smem row of this thread's window

    // per-column valid-count in x (analytic)
    float fcx[4];
    #pragma unroll
    for (int m = 0; m < 4; ++m) {
        const int gj = gj0 + m;
        fcx[m] = (float)(min(gj, 2) + min(WW - 1 - gj, 2) + 1);
    }

    float4 rhs[5], rhq[5], rc[3];
    float lsum = 0.0f;

    #pragma unroll
    for (int k = 0; k < 12; ++k) {
        const int r = r0 + k;
        // 12 floats covering window cols, 3 conflict-free LDS.128
        const float4 A = *reinterpret_cast<const float4*>(&sp[r][j * 4]);
        const float4 B = *reinterpret_cast<const float4*>(&sp[r][j * 4 + 4]);
        const float4 C = *reinterpret_cast<const float4*>(&sp[r][j * 4 + 8]);

        // horizontal sliding window sums (5-wide) for 4 output cols
        float4 hsv, hqv;
        hsv.x = A.z + A.w + B.x + B.y + B.z;
        hsv.y = hsv.x - A.z + B.w;
        hsv.z = hsv.y - A.w + C.x;
        hsv.w = hsv.z - B.x + C.y;
        const float qAz = A.z * A.z, qAw = A.w * A.w;
        const float qBx = B.x * B.x, qBy = B.y * B.y, qBz = B.z * B.z, qBw = B.w * B.w;
        const float qCx = C.x * C.x, qCy = C.y * C.y;
        hqv.x = qAz + qAw + qBx + qBy + qBz;
        hqv.y = hqv.x - qAz + qBw;
        hqv.z = hqv.y - qAw + qCx;
        hqv.w = hqv.z - qBx + qCy;

        rhs[k % 5] = hsv;
        rhq[k % 5] = hqv;
        rc[k % 3]  = B;

        if (k >= 4) {
            const int gi = row0 + r0 + k - 4;   // global output row
            float4 S, Q;
            S.x = rhs[0].x + rhs[1].x + rhs[2].x + rhs[3].x + rhs[4].x;
            S.y = rhs[0].y + rhs[1].y + rhs[2].y + rhs[3].y + rhs[4].y;
            S.z = rhs[0].z + rhs[1].z + rhs[2].z + rhs[3].z + rhs[4].z;
            S.w = rhs[0].w + rhs[1].w + rhs[2].w + rhs[3].w + rhs[4].w;
            Q.x = rhq[0].x + rhq[1].x + rhq[2].x + rhq[3].x + rhq[4].x;
            Q.y = rhq[0].y + rhq[1].y + rhq[2].y + rhq[3].y + rhq[4].y;
            Q.z = rhq[0].z + rhq[1].z + rhq[2].z + rhq[3].z + rhq[4].z;
            Q.w = rhq[0].w + rhq[1].w + rhq[2].w + rhq[3].w + rhq[4].w;
            const float4 P0 = rc[(k - 2) % 3];  // center row p values

            const float fcy = (float)(min(gi, 2) + min(HH - 1 - gi, 2) + 1);

            const float4 yv = *reinterpret_cast<const float4*>(yimg + gi * WW + gj0);
            const float4 gv = *reinterpret_cast<const float4*>(gimg + gi * WW + gj0);
            float4 w;

            {   // component macro-expansion
                #define DO_COMP(c, mi)                                                  \
                {                                                                       \
                    const float fnv = fcx[mi] * fcy;                                    \
                    const float p0  = P0.c;                                             \
                    const float acc = fmaf(fmaf(fnv, p0, -2.0f * S.c), p0, Q.c);        \
                    const float cons = 1.0f - __fdividef(acc, fnv - 1.0f);              \
                    const float y   = yv.c;                                             \
                    const float spv = fmaxf(y, 0.0f) +                                  \
                                      __logf(1.0f + __expf(-fabsf(y)));                 \
                    const float ent = 1.0f + (p0 * y - spv) * INV_LOG2;                 \
                    float ww = fmaxf(cons * ent, gv.c);                                 \
                    w.c = fmaf(1.0f - MIN_WEIGHT, ww, MIN_WEIGHT);                      \
                }
                DO_COMP(x, 0)
                DO_COMP(y, 1)
                DO_COMP(z, 2)
                DO_COMP(w, 3)
                #undef DO_COMP
            }

            *reinterpret_cast<float4*>(oimg + gi * WW + gj0) = w;
            lsum += (w.x + w.y) + (w.z + w.w);
        }
    }

    // ---- block reduction -> one partial per block (no atomics) ----
    #pragma unroll
    for (int o = 16; o; o >>= 1) lsum += __shfl_down_sync(0xffffffffu, lsum, o);
    if ((tid & 31) == 0) wsum[tid >> 5] = lsum;
    __syncthreads();
    if (tid < 8) {
        float v = wsum[tid];
        #pragma unroll
        for (int o = 4; o; o >>= 1) v += __shfl_down_sync(0xffu, v, o);
        if (tid == 0)
            g_part[img * BPI + blockIdx.y * BLOCKS_X + blockIdx.x] = v;
    }
}

// in-place per-image normalization: out *= HW / sum[img]
__global__ __launch_bounds__(256) void k_pass2(float* __restrict__ out) {
    const int img = blockIdx.y;
    __shared__ float s_scale;
    const int tid = threadIdx.x;
    if (tid < 32) {
        float v = 0.0f;
        for (int t = tid; t < BPI; t += 32) v += g_part[img * BPI + t];
        #pragma unroll
        for (int o = 16; o; o >>= 1) v += __shfl_down_sync(0xffffffffu, v, o);
        if (tid == 0) s_scale = __fdividef((float)HWI, v);
    }
    __syncthreads();
    const float scale = s_scale;
    float4* p = reinterpret_cast<float4*>(out + (long long)img * HWLL);
    const int idx = blockIdx.x * blockDim.x + tid;
    float4 v = p[idx];
    v.x *= scale; v.y *= scale; v.z *= scale; v.w *= scale;
    p[idx] = v;
}

extern "C" void kernel_launch(void* const* d_in, const int* in_sizes, int n_in,
                              void* d_out, int out_size) {
    const float* yd  = (const float*)d_in[0];
    const float* ygt = (const float*)d_in[1];
    float* out = (float*)d_out;

    dim3 b1(32, 8);
    dim3 g1(BLOCKS_X, BLOCKS_Y, NIMG);      // (6, 12, 32)
    k_pass1<<<g1, b1>>>(yd, ygt, out);

    dim3 g2(HWI / 4 / 256, NIMG);           // (576, 32)
    k_pass2<<<g2, 256>>>(out);
}

// round 3
// speedup vs baseline: 1.6902x; 1.4763x over previous
#include <cuda_runtime.h>
#include <math.h>

// Problem constants
#define HH 768
#define WW 768
#define NIMG 32
#define HWI (768 * 768)
#define HWLL (768LL * 768LL)

// Tile: 128 cols x 64 rows per block; block (32,8); thread = 4 cols x 8 rows
#define TW 128
#define TH 64
#define SW2 136          // TW + 8 (4-col halo both sides, float4 aligned)
#define SH2 68           // TH + 4
#define BLOCKS_X (WW / TW)   // 6
#define BLOCKS_Y (HH / TH)   // 12
#define BPI (BLOCKS_X * BLOCKS_Y)  // 72 blocks per image

#define MIN_WEIGHT 0.1f

__device__ float g_part[NIMG * BPI];   // every slot written each run -> no init needed

__device__ __forceinline__ float tanh_a(float x) {
    float r;
    asm("tanh.approx.f32 %0, %1;" : "=f"(r) : "f"(x));
    return r;
}
// sigmoid(x) = 0.5*tanh(x/2) + 0.5  (1 MUFU)
__device__ __forceinline__ float sigm(float x) {
    return fmaf(0.5f, tanh_a(0.5f * x), 0.5f);
}

// Horizontal 5-wide sliding sums (hs) and sum-of-squares (hq) for 4 output
// columns, reading 12 floats (3 conflict-free LDS.128) from smem row r.
#define HSQ(r, hs, hq)                                                         \
{                                                                              \
    const float4 A = *reinterpret_cast<const float4*>(&sp[r][j4]);             \
    const float4 B = *reinterpret_cast<const float4*>(&sp[r][j4 + 4]);         \
    const float4 C = *reinterpret_cast<const float4*>(&sp[r][j4 + 8]);         \
    hs.x = A.z + A.w + B.x + B.y + B.z;                                        \
    hs.y = hs.x - A.z + B.w;                                                   \
    hs.z = hs.y - A.w + C.x;                                                   \
    hs.w = hs.z - B.x + C.y;                                                   \
    const float qAz = A.z * A.z, qAw = A.w * A.w;                              \
    const float qBx = B.x * B.x, qBy = B.y * B.y;                              \
    const float qBz = B.z * B.z, qBw = B.w * B.w;                              \
    const float qCx = C.x * C.x, qCy = C.y * C.y;                              \
    hq.x = qAz + qAw + qBx + qBy + qBz;                                        \
    hq.y = hq.x - qAz + qBw;                                                   \
    hq.z = hq.y - qAw + qCx;                                                   \
    hq.w = hq.z - qBx + qCy;                                                   \
}

__global__ __launch_bounds__(256, 4) void k_pass1(
    const float* __restrict__ yd,
    const float* __restrict__ ygt,
    float* __restrict__ out)
{
    __shared__ float sp[SH2][SW2];
    __shared__ float wsum[8];

    const int img  = blockIdx.z;
    const int col0 = blockIdx.x * TW;
    const int row0 = blockIdx.y * TH;
    const float* __restrict__ yimg = yd  + (long long)img * HWLL;
    const float* __restrict__ gimg = ygt + (long long)img * HWLL;
    float* __restrict__ oimg = out + (long long)img * HWLL;

    const int tid = threadIdx.y * 32 + threadIdx.x;

    // ---- fill p = sigmoid(y) tile (halo: 2 rows, 4 cols; OOB -> 0) ----
    for (int t = tid; t < SH2 * 34; t += 256) {
        const int li = t / 34;
        const int v  = t - li * 34;
        const int gi = row0 + li - 2;
        const int gj = col0 + v * 4 - 4;
        float4 r = make_float4(0.f, 0.f, 0.f, 0.f);
        if ((unsigned)gi < (unsigned)HH && (unsigned)gj <= (unsigned)(WW - 4)) {
            float4 yv = *reinterpret_cast<const float4*>(yimg + gi * WW + gj);
            r.x = sigm(yv.x); r.y = sigm(yv.y); r.z = sigm(yv.z); r.w = sigm(yv.w);
        }
        *reinterpret_cast<float4*>(&sp[li][v * 4]) = r;
    }
    __syncthreads();

    const int j4   = threadIdx.x * 4;
    const int gj0  = col0 + j4;              // first global output column
    const int r0   = threadIdx.y * 8;        // first output row (smem row offset)

    // per-column valid-count in x (analytic)
    float fcx[4];
    #pragma unroll
    for (int m = 0; m < 4; ++m) {
        const int gj = gj0 + m;
        fcx[m] = (float)(min(gj, 2) + min(WW - 1 - gj, 2) + 1);
    }

    // Running 5x5 window sums via sliding add/subtract (no rings).
    float4 S = make_float4(0.f, 0.f, 0.f, 0.f);
    float4 Q = make_float4(0.f, 0.f, 0.f, 0.f);
    #pragma unroll
    for (int k = 0; k < 4; ++k) {
        float4 hs, hq;
        HSQ(r0 + k, hs, hq);
        S.x += hs.x; S.y += hs.y; S.z += hs.z; S.w += hs.w;
        Q.x += hq.x; Q.y += hq.y; Q.z += hq.z; Q.w += hq.w;
    }

    float lsum = 0.0f;

    #pragma unroll
    for (int o = 0; o < 8; ++o) {
        const int gi = row0 + r0 + o;
        // issue the y_gt load early (long scoreboard overlaps the LDS work)
        const float4 gv = *reinterpret_cast<const float4*>(gimg + gi * WW + gj0);

        // incoming window row
        {
            float4 hs, hq;
            HSQ(r0 + o + 4, hs, hq);
            S.x += hs.x; S.y += hs.y; S.z += hs.z; S.w += hs.w;
            Q.x += hq.x; Q.y += hq.y; Q.z += hq.z; Q.w += hq.w;
        }

        // center-row p values for the 4 output columns
        const float4 P0 = *reinterpret_cast<const float4*>(&sp[r0 + o + 2][j4 + 4]);

        const float fcy = (float)(min(gi, 2) + min(HH - 1 - gi, 2) + 1);

        float4 w;
        #define DO_COMP(c, mi)                                                  \
        {                                                                       \
            const float fnv = fcx[mi] * fcy;                                    \
            const float p0  = P0.c;                                             \
            const float acc = fmaf(fmaf(fnv, p0, -2.0f * S.c), p0, Q.c);        \
            const float cons = 1.0f - __fdividef(acc, fnv - 1.0f);              \
            /* entropy = 1 + p*log2(p) + (1-p)*log2(1-p) */                     \
            const float qq  = 1.0f - p0;                                        \
            const float l2p = __log2f(fmaxf(p0, 1e-37f));                       \
            const float l2q = __log2f(fmaxf(qq, 1e-37f));                       \
            const float ent = fmaf(p0, l2p, fmaf(qq, l2q, 1.0f));               \
            float ww = fmaxf(cons * ent, gv.c);                                 \
            w.c = fmaf(1.0f - MIN_WEIGHT, ww, MIN_WEIGHT);                      \
        }
        DO_COMP(x, 0)
        DO_COMP(y, 1)
        DO_COMP(z, 2)
        DO_COMP(w, 3)
        #undef DO_COMP

        *reinterpret_cast<float4*>(oimg + gi * WW + gj0) = w;
        lsum += (w.x + w.y) + (w.z + w.w);

        // leaving window row (skip on last iteration)
        if (o < 7) {
            float4 hs, hq;
            HSQ(r0 + o, hs, hq);
            S.x -= hs.x; S.y -= hs.y; S.z -= hs.z; S.w -= hs.w;
            Q.x -= hq.x; Q.y -= hq.y; Q.z -= hq.z; Q.w -= hq.w;
        }
    }

    // ---- block reduction -> one partial per block (no atomics) ----
    #pragma unroll
    for (int o = 16; o; o >>= 1) lsum += __shfl_down_sync(0xffffffffu, lsum, o);
    if ((tid & 31) == 0) wsum[tid >> 5] = lsum;
    __syncthreads();
    if (tid < 8) {
        float v = wsum[tid];
        #pragma unroll
        for (int o = 4; o; o >>= 1) v += __shfl_down_sync(0xffu, v, o);
        if (tid == 0)
            g_part[img * BPI + blockIdx.y * BLOCKS_X + blockIdx.x] = v;
    }
}

// in-place per-image normalization: out *= HW / sum[img]; 4 float4 per thread
__global__ __launch_bounds__(256) void k_pass2(float* __restrict__ out) {
    const int img = blockIdx.y;
    float4* p = reinterpret_cast<float4*>(out + (long long)img * HWLL);
    const int tid  = threadIdx.x;
    const int base = blockIdx.x * 1024 + tid;

    // issue data loads first so they are in flight during the reduction
    float4 a = p[base];
    float4 b = p[base + 256];
    float4 c = p[base + 512];
    float4 d = p[base + 768];

    __shared__ float s_scale;
    if (tid < 32) {
        float v = 0.0f;
        #pragma unroll
        for (int t = 0; t < 3; ++t) {
            const int idx = tid + t * 32;
            if (idx < BPI) v += g_part[img * BPI + idx];
        }
        #pragma unroll
        for (int o = 16; o; o >>= 1) v += __shfl_down_sync(0xffffffffu, v, o);
        if (tid == 0) s_scale = __fdividef((float)HWI, v);
    }
    __syncthreads();
    const float s = s_scale;

    a.x *= s; a.y *= s; a.z *= s; a.w *= s;
    b.x *= s; b.y *= s; b.z *= s; b.w *= s;
    c.x *= s; c.y *= s; c.z *= s; c.w *= s;
    d.x *= s; d.y *= s; d.z *= s; d.w *= s;
    p[base]       = a;
    p[base + 256] = b;
    p[base + 512] = c;
    p[base + 768] = d;
}

extern "C" void kernel_launch(void* const* d_in, const int* in_sizes, int n_in,
                              void* d_out, int out_size) {
    const float* yd  = (const float*)d_in[0];
    const float* ygt = (const float*)d_in[1];
    float* out = (float*)d_out;

    dim3 b1(32, 8);
    dim3 g1(BLOCKS_X, BLOCKS_Y, NIMG);      // (6, 12, 32)
    k_pass1<<<g1, b1>>>(yd, ygt, out);

    dim3 g2(HWI / 4 / 1024, NIMG);          // (144, 32)
    k_pass2<<<g2, 256>>>(out);
}